// round 17
// baseline (speedup 1.0000x reference)
#include <cuda_runtime.h>
#include <cuda_bf16.h>
#include <math.h>
#include <stdint.h>

// GCN1: 3-layer GCN over 4 graphs, shared weights, scalar-mean output.
// R17: R16 bodies (best: 1342us), restructured as a cross-graph software
//      pipeline: launch t runs op k=t-g for each graph g (9 fat launches),
//      striped block->op assignment mixes L2-bound SpMM blocks with
//      tensor-bound GEMM blocks on every SM. Per-graph buffers kill races.

#define NN 50000
#define EE 800000
#define FH 304
#define FI 128
#define NG 4
#define NB 196        // ceil(NN/256)
#define SPMM_BLKS 6250
#define GEMM_BLKS 1955  // 391 x 5

// ---------------- scratch (__device__ only; never passed as kernel args) ----
__device__ __align__(128) uint32_t g_bufAh[NG][(size_t)NN * 160]; // SpMM out bf16x2
__device__ __align__(128) float    g_bufB[NG][(size_t)NN * FH];   // GEMM out fp32
__device__ __align__(128) uint32_t g_Wh1[320 * 64];               // [Npad][K/2] bf16x2
__device__ __align__(128) uint32_t g_Wh2[320 * 160];
__device__ __align__(128) uint32_t g_Wh3[320 * 160];
__device__ float g_ns[NG][NN];
__device__ float g_nd[NG][NN];
__device__ int   g_deg_s[NG][NN];
__device__ int   g_deg_d[NG][NN];
__device__ int   g_rowoff[NG][NN + 1];
__device__ int   g_cursor[NG][NN];
__device__ int   g_csr[NG][EE];
__device__ int   g_bsum[NG][256];
__device__ int   g_boff[NG][256];
__device__ double g_sum;

// ---------------- helpers ----------------------------------------------------
__device__ __forceinline__ uint32_t packbf(float x, float y) {
    __nv_bfloat162 b = __float22bfloat162_rn(make_float2(x, y));
    return *(uint32_t*)&b;
}
__device__ __forceinline__ void ldmx4(uint32_t& r0, uint32_t& r1,
                                      uint32_t& r2, uint32_t& r3, uint32_t addr) {
    asm volatile("ldmatrix.sync.aligned.m8n8.x4.shared.b16 {%0,%1,%2,%3}, [%4];"
                 : "=r"(r0), "=r"(r1), "=r"(r2), "=r"(r3) : "r"(addr));
}
__device__ __forceinline__ void mma16(float* d, const uint32_t* a, const uint32_t* b) {
    asm volatile("mma.sync.aligned.m16n8k16.row.col.f32.bf16.bf16.f32 "
                 "{%0,%1,%2,%3}, {%4,%5,%6,%7}, {%8,%9}, {%0,%1,%2,%3};"
                 : "+f"(d[0]), "+f"(d[1]), "+f"(d[2]), "+f"(d[3])
                 : "r"(a[0]), "r"(a[1]), "r"(a[2]), "r"(a[3]),
                   "r"(b[0]), "r"(b[1]));
}

// ---------------- setup kernels ----------------------------------------------
__global__ void k_init() { g_sum = 0.0; }

__global__ void k_prep_wh(const float* __restrict__ W, int sel, int K, int Kp2) {
    int id = blockIdx.x * blockDim.x + threadIdx.x;
    if (id >= 320 * Kp2) return;
    int n = id / Kp2, kw = id % Kp2;
    int k = 2 * kw;
    float v0 = (k < K && n < FH) ? W[(size_t)k * FH + n] : 0.f;
    float v1 = (k + 1 < K && n < FH) ? W[(size_t)(k + 1) * FH + n] : 0.f;
    uint32_t* dst = (sel == 0) ? g_Wh1 : (sel == 1) ? g_Wh2 : g_Wh3;
    dst[(size_t)n * Kp2 + kw] = packbf(v0, v1);
}

__global__ void k_zero() {
    int g = blockIdx.y;
    int i = blockIdx.x * blockDim.x + threadIdx.x;
    if (i < NN) { g_deg_s[g][i] = 0; g_deg_d[g][i] = 0; }
}

__global__ void k_deg(const int* __restrict__ s0, const int* __restrict__ d0,
                      const int* __restrict__ s1, const int* __restrict__ d1,
                      const int* __restrict__ s2, const int* __restrict__ d2,
                      const int* __restrict__ s3, const int* __restrict__ d3) {
    int g = blockIdx.y;
    const int* s = (g == 0) ? s0 : (g == 1) ? s1 : (g == 2) ? s2 : s3;
    const int* d = (g == 0) ? d0 : (g == 1) ? d1 : (g == 2) ? d2 : d3;
    int e = blockIdx.x * blockDim.x + threadIdx.x;
    if (e < EE) {
        atomicAdd(&g_deg_s[g][s[e]], 1);
        atomicAdd(&g_deg_d[g][d[e]], 1);
    }
}

__global__ void k_scan1() {
    int g = blockIdx.y, t = threadIdx.x;
    int i = blockIdx.x * 256 + t;
    __shared__ int sm[256];
    sm[t] = (i < NN) ? g_deg_d[g][i] : 0;
    __syncthreads();
    for (int o = 128; o > 0; o >>= 1) {
        if (t < o) sm[t] += sm[t + o];
        __syncthreads();
    }
    if (t == 0) g_bsum[g][blockIdx.x] = sm[0];
}

__global__ void k_scan2() {
    int g = blockIdx.y, t = threadIdx.x;
    int v = (t < NB) ? g_bsum[g][t] : 0;
    __shared__ int sm[256];
    sm[t] = v;
    __syncthreads();
    for (int o = 1; o < 256; o <<= 1) {
        int a = (t >= o) ? sm[t - o] : 0;
        __syncthreads();
        sm[t] += a;
        __syncthreads();
    }
    g_boff[g][t] = sm[t] - v;  // exclusive
}

__global__ void k_scan3() {
    int g = blockIdx.y, t = threadIdx.x;
    int i = blockIdx.x * 256 + t;
    int d = (i < NN) ? g_deg_d[g][i] : 0;
    __shared__ int sm[256];
    sm[t] = d;
    __syncthreads();
    for (int o = 1; o < 256; o <<= 1) {
        int a = (t >= o) ? sm[t - o] : 0;
        __syncthreads();
        sm[t] += a;
        __syncthreads();
    }
    int off = g_boff[g][blockIdx.x] + sm[t] - d;  // exclusive
    if (i < NN) {
        g_rowoff[g][i] = off;
        g_cursor[g][i] = off;
        g_nd[g][i] = rsqrtf((float)max(d, 1));
        g_ns[g][i] = rsqrtf((float)max(g_deg_s[g][i], 1));
    }
    if (blockIdx.x == 0 && t == 0) g_rowoff[g][NN] = EE;
}

__global__ void k_scatter(const int* __restrict__ s0, const int* __restrict__ d0,
                          const int* __restrict__ s1, const int* __restrict__ d1,
                          const int* __restrict__ s2, const int* __restrict__ d2,
                          const int* __restrict__ s3, const int* __restrict__ d3) {
    int g = blockIdx.y;
    const int* s = (g == 0) ? s0 : (g == 1) ? s1 : (g == 2) ? s2 : s3;
    const int* d = (g == 0) ? d0 : (g == 1) ? d1 : (g == 2) ? d2 : d3;
    int e = blockIdx.x * blockDim.x + threadIdx.x;
    if (e < EE) {
        int p = atomicAdd(&g_cursor[g][d[e]], 1);
        g_csr[g][p] = s[e];
    }
}

// ---------------- pipelined megakernel ---------------------------------------
struct OpDesc { int type, g, a, b, c, d; const float* p; };
// spmm: a=use_ext, b=F, c=wstride, p=X[g] (or null)
// gemm: a=wsel, b=NC, c=wstride, d=dosum, p=bias
struct Cfg { OpDesc ops[4]; int nops; };

// Warp-per-dst SpMM (R16 body): fp32 gathers, bf16x2 output, unroll-2.
__device__ __forceinline__ void spmm_body(int rb, const OpDesc& op) {
    int g = op.g, use_ext = op.a, F = op.b, wstride = op.c;
    const float* __restrict__ hin = use_ext ? op.p : (const float*)g_bufB[g];
    int n = rb * 8 + (threadIdx.x >> 5);
    int lane = threadIdx.x & 31;
    int beg = g_rowoff[g][n];
    int end = g_rowoff[g][n + 1];
    float4 a0 = make_float4(0.f, 0.f, 0.f, 0.f);
    float4 a1 = make_float4(0.f, 0.f, 0.f, 0.f);
    float4 a2 = make_float4(0.f, 0.f, 0.f, 0.f);
    int j = beg;
    for (; j + 1 < end; j += 2) {
        int sA = g_csr[g][j], sB = g_csr[g][j + 1];
        float wA = g_ns[g][sA], wB = g_ns[g][sB];
        const float4* rA = (const float4*)(hin + (size_t)sA * F);
        const float4* rB = (const float4*)(hin + (size_t)sB * F);
        float4 uA = rA[lane], uB = rB[lane];
        a0.x += wA * uA.x + wB * uB.x;  a0.y += wA * uA.y + wB * uB.y;
        a0.z += wA * uA.z + wB * uB.z;  a0.w += wA * uA.w + wB * uB.w;
        if (F > 128) {
            float4 vA = rA[lane + 32], vB = rB[lane + 32];
            a1.x += wA * vA.x + wB * vB.x;  a1.y += wA * vA.y + wB * vB.y;
            a1.z += wA * vA.z + wB * vB.z;  a1.w += wA * vA.w + wB * vB.w;
            if (lane < 12) {
                float4 tA = rA[lane + 64], tB = rB[lane + 64];
                a2.x += wA * tA.x + wB * tB.x;  a2.y += wA * tA.y + wB * tB.y;
                a2.z += wA * tA.z + wB * tB.z;  a2.w += wA * tA.w + wB * tB.w;
            }
        }
    }
    if (j < end) {
        int s = g_csr[g][j];
        float w = g_ns[g][s];
        const float4* r = (const float4*)(hin + (size_t)s * F);
        float4 u = r[lane];
        a0.x += w * u.x;  a0.y += w * u.y;  a0.z += w * u.z;  a0.w += w * u.w;
        if (F > 128) {
            float4 v = r[lane + 32];
            a1.x += w * v.x;  a1.y += w * v.y;  a1.z += w * v.z;  a1.w += w * v.w;
            if (lane < 12) {
                float4 t2 = r[lane + 64];
                a2.x += w * t2.x;  a2.y += w * t2.y;  a2.z += w * t2.z;  a2.w += w * t2.w;
            }
        }
    }
    float nd = g_nd[g][n];
    uint32_t* o = g_bufAh[g] + (size_t)n * wstride;
    {
        uint32_t p0 = packbf(a0.x * nd, a0.y * nd);
        uint32_t p1 = packbf(a0.z * nd, a0.w * nd);
        *(uint2*)(o + 2 * lane) = make_uint2(p0, p1);
    }
    if (F > 128) {
        uint32_t p0 = packbf(a1.x * nd, a1.y * nd);
        uint32_t p1 = packbf(a1.z * nd, a1.w * nd);
        *(uint2*)(o + 64 + 2 * lane) = make_uint2(p0, p1);
        if (lane < 12) {
            uint32_t q0 = packbf(a2.x * nd, a2.y * nd);
            uint32_t q1 = packbf(a2.z * nd, a2.w * nd);
            *(uint2*)(o + 128 + 2 * lane) = make_uint2(q0, q1);
        } else if (lane < 16) {
            *(uint2*)(o + 128 + 2 * lane) = make_uint2(0u, 0u);
        }
    }
}

#define PADW 20  // 16 words + 4 pad

// bf16 mma GEMM with ldmatrix fragments (R16 body).
__device__ __forceinline__ void gemm_body(int rb, const OpDesc& op,
                                          uint32_t (*As)[PADW], uint32_t (*Bs)[PADW],
                                          float* wsum) {
    int gsel = op.g, wsel = op.a, NC = op.b, wstride = op.c, dosum = op.d;
    const float* __restrict__ bias = op.p;
    const uint32_t* __restrict__ Wh = (wsel == 0) ? g_Wh1 : (wsel == 1) ? g_Wh2 : g_Wh3;
    const uint32_t* __restrict__ Abuf = g_bufAh[gsel];
    float* __restrict__ Cbuf = g_bufB[gsel];
    const int Kp2 = NC * 16;

    int tid = threadIdx.x, wid = tid >> 5, lane = tid & 31;
    int wm = wid & 3, wn = wid >> 2;
    int rowBase = (rb % 391) * 128;
    int colBase = (rb / 391) * 64;

    float acc[2][4][4];
#pragma unroll
    for (int mi = 0; mi < 2; mi++)
#pragma unroll
        for (int ni = 0; ni < 4; ni++)
#pragma unroll
            for (int q = 0; q < 4; q++) acc[mi][ni][q] = 0.f;

    int lg = lane >> 3, lr = lane & 7;
    uint32_t sAs = (uint32_t)__cvta_generic_to_shared(&As[0][0]);
    uint32_t sBs = (uint32_t)__cvta_generic_to_shared(&Bs[0][0]);
    uint32_t aAddr[2], bAddr[2];
#pragma unroll
    for (int mi = 0; mi < 2; mi++)
        aAddr[mi] = sAs + (((wm * 32 + mi * 16 + (lg & 1) * 8 + lr) * PADW
                            + (lg >> 1) * 4) << 2);
#pragma unroll
    for (int nip = 0; nip < 2; nip++)
        bAddr[nip] = sBs + (((wn * 32 + (nip * 2 + (lg >> 1)) * 8 + lr) * PADW
                             + (lg & 1) * 4) << 2);

    int ar = tid >> 2, aw = tid & 3;
    int br = tid >> 2, bw = tid & 3;
    uint4 aU[2], bU;

    {   // prefetch chunk 0
#pragma unroll
        for (int j = 0; j < 2; j++) {
            int gr = rowBase + ar + j * 64;
            aU[j] = (gr < NN)
                ? *(const uint4*)(Abuf + (size_t)gr * wstride + aw * 4)
                : make_uint4(0u, 0u, 0u, 0u);
        }
        bU = *(const uint4*)(Wh + (size_t)(colBase + br) * Kp2 + bw * 4);
    }

    for (int c = 0; c < NC; c++) {
#pragma unroll
        for (int j = 0; j < 2; j++)
            *(uint4*)&As[ar + j * 64][aw * 4] = aU[j];
        *(uint4*)&Bs[br][bw * 4] = bU;
        __syncthreads();

        if (c + 1 < NC) {
            int kw0 = (c + 1) * 16;
#pragma unroll
            for (int j = 0; j < 2; j++) {
                int gr = rowBase + ar + j * 64;
                aU[j] = (gr < NN)
                    ? *(const uint4*)(Abuf + (size_t)gr * wstride + kw0 + aw * 4)
                    : make_uint4(0u, 0u, 0u, 0u);
            }
            bU = *(const uint4*)(Wh + (size_t)(colBase + br) * Kp2 + kw0 + bw * 4);
        }

#pragma unroll
        for (int kw = 0; kw < 16; kw += 8) {
            uint32_t af[2][4], bf[4][2];
#pragma unroll
            for (int mi = 0; mi < 2; mi++)
                ldmx4(af[mi][0], af[mi][1], af[mi][2], af[mi][3],
                      aAddr[mi] + (kw << 2));
#pragma unroll
            for (int nip = 0; nip < 2; nip++)
                ldmx4(bf[nip * 2][0], bf[nip * 2][1],
                      bf[nip * 2 + 1][0], bf[nip * 2 + 1][1],
                      bAddr[nip] + (kw << 2));
#pragma unroll
            for (int mi = 0; mi < 2; mi++)
#pragma unroll
                for (int ni = 0; ni < 4; ni++)
                    mma16(acc[mi][ni], af[mi], bf[ni]);
        }
        __syncthreads();
    }

    float lsum = 0.f;
    int gq = lane >> 2, cc = lane & 3;
#pragma unroll
    for (int mi = 0; mi < 2; mi++) {
        int r0 = rowBase + wm * 32 + mi * 16 + gq;
#pragma unroll
        for (int ni = 0; ni < 4; ni++) {
            int c0 = colBase + wn * 32 + ni * 8 + cc * 2;
            if (c0 < FH) {
                float bz0 = bias[c0], bz1 = bias[c0 + 1];
                float v0 = fmaxf(acc[mi][ni][0] + bz0, 0.f);
                float v1 = fmaxf(acc[mi][ni][1] + bz1, 0.f);
                float v2 = fmaxf(acc[mi][ni][2] + bz0, 0.f);
                float v3 = fmaxf(acc[mi][ni][3] + bz1, 0.f);
                if (dosum) {
                    if (r0 < NN)     lsum += v0 + v1;
                    if (r0 + 8 < NN) lsum += v2 + v3;
                } else {
                    if (r0 < NN)
                        *(float2*)(Cbuf + (size_t)r0 * FH + c0) = make_float2(v0, v1);
                    if (r0 + 8 < NN)
                        *(float2*)(Cbuf + (size_t)(r0 + 8) * FH + c0) = make_float2(v2, v3);
                }
            }
        }
    }
    if (dosum) {
#pragma unroll
        for (int o = 16; o > 0; o >>= 1) lsum += __shfl_down_sync(0xffffffffu, lsum, o);
        if (lane == 0) wsum[wid] = lsum;
        __syncthreads();
        if (tid == 0) {
            double tot = 0.0;
#pragma unroll
            for (int w = 0; w < 8; w++) tot += (double)wsum[w];
            atomicAdd(&g_sum, tot);
        }
    }
}

__global__ void __launch_bounds__(256)
k_mega(Cfg cfg) {
    __shared__ uint32_t As[128][PADW];
    __shared__ uint32_t Bs[64][PADW];
    __shared__ float wsum[8];
    int oi = blockIdx.x % cfg.nops;
    int rb = blockIdx.x / cfg.nops;
    const OpDesc& op = cfg.ops[oi];
    if (op.type == 0) {
        if (rb >= SPMM_BLKS) return;
        spmm_body(rb, op);
    } else {
        if (rb >= GEMM_BLKS) return;
        gemm_body(rb, op, As, Bs, wsum);
    }
}

__global__ void k_final(float* __restrict__ out) {
    out[0] = (float)(g_sum / (4.0 * NN * FH));
}

// ---------------- launch -----------------------------------------------------
extern "C" void kernel_launch(void* const* d_in, const int* in_sizes, int n_in,
                              void* d_out, int out_size) {
    const float* X[4];   int nx = 0;
    const int*   EDG[8]; int ne = 0;
    const float* W[3] = {0, 0, 0};
    const float* Bv[3]; int nb = 0;
    int nw2 = 0;
    for (int i = 0; i < n_in; i++) {
        int sz = in_sizes[i];
        if (sz == 6400000)      X[nx++]   = (const float*)d_in[i];
        else if (sz == 800000)  EDG[ne++] = (const int*)d_in[i];
        else if (sz == 38912)   W[0] = (const float*)d_in[i];
        else if (sz == 92416)   { W[1 + nw2] = (const float*)d_in[i]; nw2++; }
        else if (sz == 304)     Bv[nb++] = (const float*)d_in[i];
    }
    float* out = (float*)d_out;

    k_init<<<1, 1>>>();
    k_prep_wh<<<(320 * 64 + 255) / 256, 256>>>(W[0], 0, 128, 64);
    k_prep_wh<<<(320 * 160 + 255) / 256, 256>>>(W[1], 1, 304, 160);
    k_prep_wh<<<(320 * 160 + 255) / 256, 256>>>(W[2], 2, 304, 160);

    // batched CSR build for all 4 graphs
    k_zero<<<dim3(NB, NG), 256>>>();
    k_deg<<<dim3(EE / 256, NG), 256>>>(EDG[0], EDG[1], EDG[2], EDG[3],
                                       EDG[4], EDG[5], EDG[6], EDG[7]);
    k_scan1<<<dim3(NB, NG), 256>>>();
    k_scan2<<<dim3(1, NG), 256>>>();
    k_scan3<<<dim3(NB, NG), 256>>>();
    k_scatter<<<dim3(EE / 256, NG), 256>>>(EDG[0], EDG[1], EDG[2], EDG[3],
                                           EDG[4], EDG[5], EDG[6], EDG[7]);

    // pipelined main chain: op k of graph g runs in launch t = k + g
    for (int t = 0; t < 9; t++) {
        Cfg cfg;
        int no = 0, maxc = 0;
        for (int g = 0; g < NG; g++) {
            int k = t - g;
            if (k < 0 || k > 5) continue;
            OpDesc o; o.g = g; o.d = 0;
            if ((k & 1) == 0) {           // spmm, layer k/2
                o.type = 0;
                if (k == 0) { o.a = 1; o.b = FI; o.c = 64;  o.p = X[g]; }
                else        { o.a = 0; o.b = FH; o.c = 160; o.p = 0; }
                if (SPMM_BLKS > maxc) maxc = SPMM_BLKS;
            } else {                      // gemm, layer (k-1)/2
                int layer = (k - 1) / 2;
                o.type = 1;
                o.a = layer;
                o.b = (layer == 0) ? 4 : 10;
                o.c = (layer == 0) ? 64 : 160;
                o.d = (layer == 2) ? 1 : 0;
                o.p = Bv[layer];
                if (GEMM_BLKS > maxc) maxc = GEMM_BLKS;
            }
            cfg.ops[no++] = o;
        }
        cfg.nops = no;
        k_mega<<<no * maxc, 256>>>(cfg);
    }

    k_final<<<1, 1>>>(out);
}